// round 4
// baseline (speedup 1.0000x reference)
#include <cuda_runtime.h>
#include <cuda_bf16.h>

// Problem constants
#define BATCH 4096
#define SEQ   512
#define HID   32
#define NB    2            // batch elements per warp
#define WPB   2            // warps per block -> 1024 blocks x 64 thr = 2048 warps
#define KREG  10           // k-slices of Whh kept in registers (rest via smem)

// Scratch (device globals are the allowed scratch mechanism)
__device__ ulonglong2 g_W1p[32 * 32];     // packed Whh1: [k][j] -> (wIF, wGO) u64 pairs
__device__ float  g_hf[HID * BATCH];      // final h of cell1, layout [j][b]
__device__ float  g_cf[HID * BATCH];      // final c of cell1, layout [j][b]

using u64 = unsigned long long;

// ---- packed f32x2 helpers (FFMA2 path, PTX-only) ----
__device__ __forceinline__ u64 pack2(float lo, float hi) {
    u64 r; asm("mov.b64 %0, {%1, %2};" : "=l"(r) : "f"(lo), "f"(hi)); return r;
}
__device__ __forceinline__ void unpack2(u64 v, float& lo, float& hi) {
    asm("mov.b64 {%0, %1}, %2;" : "=f"(lo), "=f"(hi) : "l"(v));
}
__device__ __forceinline__ u64 fma2(u64 a, u64 b, u64 c) {
    u64 d; asm("fma.rn.f32x2 %0, %1, %2, %3;" : "=l"(d) : "l"(a), "l"(b), "l"(c)); return d;
}

// ---- fast, accurate activations (MUFU EX2 + RCP; ~1e-6 abs err) ----
__device__ __forceinline__ float sigf(float v) {
    return __fdividef(1.0f, 1.0f + __expf(-v));
}
__device__ __forceinline__ float tanhf_fast(float v) {
    return __fdividef(2.0f, 1.0f + __expf(-2.0f * v)) - 1.0f;
}

// ---------------------------------------------------------------------------
// Kernel 0: pack Whh1 [128,32] row-major into [k][j] (wIF,wGO) u64 pairs
// ---------------------------------------------------------------------------
__global__ void pack_kernel(const float* __restrict__ Whh1) {
    int idx = blockIdx.x * blockDim.x + threadIdx.x;   // 0..1023
    if (idx < 1024) {
        int k = idx >> 5;
        int j = idx & 31;
        ulonglong2 w;
        w.x = pack2(Whh1[(0  + j) * HID + k], Whh1[(32 + j) * HID + k]);  // (i,f)
        w.y = pack2(Whh1[(64 + j) * HID + k], Whh1[(96 + j) * HID + k]);  // (g,o)
        g_W1p[idx] = w;                   // idx = k*32 + j
    }
}

// ---------------------------------------------------------------------------
// Kernel 1: sequential scan. 2 warps/block (independent), lane = hidden unit
// j, NB=2 batch elements per warp. Gate pairs (i,f)/(g,o) via fma.rn.f32x2.
// One shared weight stage per block serves both warps; per-warp Hs buffers
// hold duplicated h pairs read via broadcast LDS.128. No inter-warp sync in
// the hot loop.
// ---------------------------------------------------------------------------
__global__ void __launch_bounds__(WPB * 32) scan_kernel(
    const float* __restrict__ x,
    const float* __restrict__ h0,  const float* __restrict__ c0,
    const float* __restrict__ Wih1,
    const float* __restrict__ bih1, const float* __restrict__ bhh1)
{
    __shared__ ulonglong2 Ws2[(32 - KREG) * 32];   // [(k-KREG)][j] = (wIF, wGO), shared by both warps
    __shared__ ulonglong2 Hs[WPB][2][32];          // [warp][buf][k] = ((hA,hA),(hB,hB))

    const int j  = threadIdx.x & 31;      // lane = hidden unit
    const int w  = threadIdx.x >> 5;      // warp in block
    const int b0 = (blockIdx.x * WPB + w) * NB;

    // Weight registers for k = 0..KREG-1
    u64 wIFr[KREG], wGOr[KREG];
    #pragma unroll
    for (int k = 0; k < KREG; k++) {
        ulonglong2 ww = g_W1p[k * 32 + j];
        wIFr[k] = ww.x;
        wGOr[k] = ww.y;
    }
    // Remaining k-slices staged once into block-shared smem (warp 0 only)
    if (w == 0) {
        #pragma unroll
        for (int k = KREG; k < 32; k++)
            Ws2[(k - KREG) * 32 + j] = g_W1p[k * 32 + j];
    }

    // Per-lane constants: combined bias and input weight, gate-paired
    const u64 biasIF = pack2(bih1[0  + j] + bhh1[0  + j], bih1[32 + j] + bhh1[32 + j]);
    const u64 biasGO = pack2(bih1[64 + j] + bhh1[64 + j], bih1[96 + j] + bhh1[96 + j]);
    const u64 wihIF  = pack2(Wih1[0  + j], Wih1[32 + j]);
    const u64 wihGO  = pack2(Wih1[64 + j], Wih1[96 + j]);

    // Carry c in registers; h lives in the per-warp smem stage
    float c[NB];
    #pragma unroll
    for (int b = 0; b < NB; b++) c[b] = c0[(b0 + b) * HID + j];

    {
        float ha = h0[(b0 + 0) * HID + j];
        float hb = h0[(b0 + 1) * HID + j];
        ulonglong2 hq;
        hq.x = pack2(ha, ha);
        hq.y = pack2(hb, hb);
        Hs[w][0][j] = hq;
    }

    // lanes 0..NB-1 hold x[t][b0+lane]; prefetch one step ahead
    float xc = (j < NB) ? x[b0 + j] : 0.0f;
    __syncthreads();    // weight stage + initial Hs visible

    #pragma unroll 1
    for (int t = 0; t < SEQ; t++) {
        const int rb = t & 1;

        float xn = 0.0f;
        if (j < NB && t + 1 < SEQ) xn = x[(t + 1) * BATCH + b0 + j];

        u64 aIF[NB], aGO[NB];
        #pragma unroll
        for (int b = 0; b < NB; b++) {
            float xb = __shfl_sync(0xffffffffu, xc, b);
            u64 xd = pack2(xb, xb);
            aIF[b] = fma2(xd, wihIF, biasIF);
            aGO[b] = fma2(xd, wihGO, biasGO);
        }

        // recurrent matvec: per k, 1 broadcast LDS.128 (both batches' h) +
        // 4 FFMA2; weights from registers (k<KREG) or shared LDS.128.
        #pragma unroll
        for (int k = 0; k < 32; k++) {
            u64 wIF, wGO;
            if (k < KREG) {
                wIF = wIFr[k];
                wGO = wGOr[k];
            } else {
                ulonglong2 ww = Ws2[(k - KREG) * 32 + j];
                wIF = ww.x;
                wGO = ww.y;
            }
            ulonglong2 hq = Hs[w][rb][k];     // broadcast, pre-paired
            aIF[0] = fma2(hq.x, wIF, aIF[0]);
            aGO[0] = fma2(hq.x, wGO, aGO[0]);
            aIF[1] = fma2(hq.y, wIF, aIF[1]);
            aGO[1] = fma2(hq.y, wGO, aGO[1]);
        }

        float hn[NB];
        #pragma unroll
        for (int b = 0; b < NB; b++) {
            float ai, af, ag, ao;
            unpack2(aIF[b], ai, af);
            unpack2(aGO[b], ag, ao);
            float ig = sigf(ai);
            float fg = sigf(af);
            float gg = tanhf_fast(ag);
            float og = sigf(ao);
            c[b]  = fmaf(fg, c[b], ig * gg);
            hn[b] = og * tanhf_fast(c[b]);
        }

        {
            ulonglong2 hq;
            hq.x = pack2(hn[0], hn[0]);
            hq.y = pack2(hn[1], hn[1]);
            Hs[w][rb ^ 1][j] = hq;
        }
        xc = xn;
        __syncwarp();
    }

    // SEQ even -> final h landed in buffer 0. Write [j][b] for the tail.
    #pragma unroll
    for (int b = 0; b < NB; b++) {
        ulonglong2 hq = Hs[w][0][j];
        float lo, hi;
        unpack2((b & 1) ? hq.y : hq.x, lo, hi);
        g_hf[j * BATCH + b0 + b] = lo;
        g_cf[j * BATCH + b0 + b] = c[b];
    }
}

// ---------------------------------------------------------------------------
// Kernel 2: cell 2 (input = hidden = hf, cell = cf) + FC. One thread per batch.
// Wih2 + Whh2 folded into a single [128,32] matrix.
// ---------------------------------------------------------------------------
__global__ void __launch_bounds__(128) tail_kernel(
    const float* __restrict__ Wih2, const float* __restrict__ Whh2,
    const float* __restrict__ bih2, const float* __restrict__ bhh2,
    const float* __restrict__ Wfc,  const float* __restrict__ bfc,
    float* __restrict__ out)
{
    __shared__ float W2s[128 * 32];
    __shared__ float b2s[128];
    __shared__ float wfcs[32];
    const int tid = threadIdx.x;

    for (int i = tid; i < 128 * 32; i += 128) W2s[i] = Wih2[i] + Whh2[i];
    if (tid < 128) b2s[tid] = bih2[tid] + bhh2[tid];
    if (tid < 32)  wfcs[tid] = Wfc[tid];
    __syncthreads();

    const int b = blockIdx.x * 128 + tid;

    float h[HID];
    #pragma unroll
    for (int k = 0; k < HID; k++) h[k] = g_hf[k * BATCH + b];   // coalesced

    float acc_out = bfc[0];
    #pragma unroll
    for (int jj = 0; jj < HID; jj++) {
        float ai = b2s[0  + jj];
        float af = b2s[32 + jj];
        float ag = b2s[64 + jj];
        float ao = b2s[96 + jj];
        #pragma unroll
        for (int k = 0; k < HID; k++) {
            float hk = h[k];
            ai = fmaf(hk, W2s[(0  + jj) * HID + k], ai);
            af = fmaf(hk, W2s[(32 + jj) * HID + k], af);
            ag = fmaf(hk, W2s[(64 + jj) * HID + k], ag);
            ao = fmaf(hk, W2s[(96 + jj) * HID + k], ao);
        }
        float cf = g_cf[jj * BATCH + b];
        float cn = fmaf(sigf(af), cf, sigf(ai) * tanhf_fast(ag));
        float hn = sigf(ao) * tanhf_fast(cn);
        acc_out = fmaf(hn, wfcs[jj], acc_out);
    }
    out[b] = acc_out;
}

// ---------------------------------------------------------------------------
// kernel_launch: pack -> scan -> tail (default stream, graph-capturable)
// Input order: x,h0,c0,h1,c1,Wih1,Whh1,bih1,bhh1,Wih2,Whh2,bih2,bhh2,Wfc,bfc
// ---------------------------------------------------------------------------
extern "C" void kernel_launch(void* const* d_in, const int* in_sizes, int n_in,
                              void* d_out, int out_size)
{
    const float* x    = (const float*)d_in[0];
    const float* h0   = (const float*)d_in[1];
    const float* c0   = (const float*)d_in[2];
    const float* Wih1 = (const float*)d_in[5];
    const float* Whh1 = (const float*)d_in[6];
    const float* bih1 = (const float*)d_in[7];
    const float* bhh1 = (const float*)d_in[8];
    const float* Wih2 = (const float*)d_in[9];
    const float* Whh2 = (const float*)d_in[10];
    const float* bih2 = (const float*)d_in[11];
    const float* bhh2 = (const float*)d_in[12];
    const float* Wfc  = (const float*)d_in[13];
    const float* bfc  = (const float*)d_in[14];
    float* out = (float*)d_out;

    pack_kernel<<<8, 128>>>(Whh1);
    scan_kernel<<<BATCH / (NB * WPB), WPB * 32>>>(x, h0, c0, Wih1, bih1, bhh1);
    tail_kernel<<<BATCH / 128, 128>>>(Wih2, Whh2, bih2, bhh2, Wfc, bfc, out);
}

// round 5
// speedup vs baseline: 1.0674x; 1.0674x over previous
#include <cuda_runtime.h>
#include <cuda_bf16.h>

// Problem constants
#define BATCH 4096
#define SEQ   512
#define HID   32
#define NB    2            // batch elements per warp
#define WPB   2            // warps per block -> 1024 blocks x 64 thr = 2048 warps
#define KREG  20           // k-slices of Whh kept in registers (rest via smem)

#define L2E   1.4426950408889634f    // log2(e)

// Scratch (device globals are the allowed scratch mechanism)
__device__ ulonglong2 g_W1p[32 * 32];     // packed SCALED Whh1: [k][j] -> (wIF, wGO)
__device__ float  g_hf[HID * BATCH];      // final h of cell1, layout [j][b]
__device__ float  g_cf[HID * BATCH];      // final c of cell1, layout [j][b]

using u64 = unsigned long long;

// ---- packed f32x2 helpers (FFMA2 path, PTX-only) ----
__device__ __forceinline__ u64 pack2(float lo, float hi) {
    u64 r; asm("mov.b64 %0, {%1, %2};" : "=l"(r) : "f"(lo), "f"(hi)); return r;
}
__device__ __forceinline__ void unpack2(u64 v, float& lo, float& hi) {
    asm("mov.b64 {%0, %1}, %2;" : "=f"(lo), "=f"(hi) : "l"(v));
}
__device__ __forceinline__ u64 fma2(u64 a, u64 b, u64 c) {
    u64 d; asm("fma.rn.f32x2 %0, %1, %2, %3;" : "=l"(d) : "l"(a), "l"(b), "l"(c)); return d;
}

// ---- raw MUFU helpers ----
__device__ __forceinline__ float ex2f(float v) {
    float r; asm("ex2.approx.f32 %0, %1;" : "=f"(r) : "f"(v)); return r;
}
__device__ __forceinline__ float rcpf(float v) {
    float r; asm("rcp.approx.f32 %0, %1;" : "=f"(r) : "f"(v)); return r;
}
// a_scaled = -log2(e) * a          -> returns sigmoid(a)
__device__ __forceinline__ float sig_s(float a_scaled) {
    return rcpf(1.0f + ex2f(a_scaled));
}
// a_scaled = -2*log2(e) * a        -> returns tanh(a)
__device__ __forceinline__ float tanh_s(float a_scaled) {
    return fmaf(2.0f, rcpf(1.0f + ex2f(a_scaled)), -1.0f);
}

// ---- exact-path activations for the tail kernel (unchanged math) ----
__device__ __forceinline__ float sigf(float v) {
    return __fdividef(1.0f, 1.0f + __expf(-v));
}
__device__ __forceinline__ float tanhf_fast(float v) {
    return __fdividef(2.0f, 1.0f + __expf(-2.0f * v)) - 1.0f;
}

// ---------------------------------------------------------------------------
// Kernel 0: pack Whh1 [128,32] into [k][j] (wIF,wGO) u64 pairs with the
// activation scale factors folded in: i,f,o rows scaled by -log2(e), g row
// by -2*log2(e).
// ---------------------------------------------------------------------------
__global__ void pack_kernel(const float* __restrict__ Whh1) {
    int idx = blockIdx.x * blockDim.x + threadIdx.x;   // 0..1023
    if (idx < 1024) {
        int k = idx >> 5;
        int j = idx & 31;
        ulonglong2 w;
        w.x = pack2(-L2E        * Whh1[(0  + j) * HID + k],
                    -L2E        * Whh1[(32 + j) * HID + k]);   // (i,f)
        w.y = pack2(-2.0f * L2E * Whh1[(64 + j) * HID + k],
                    -L2E        * Whh1[(96 + j) * HID + k]);   // (g,o)
        g_W1p[idx] = w;                   // idx = k*32 + j
    }
}

// ---------------------------------------------------------------------------
// Kernel 1: sequential scan. 2 warps/block (independent), lane = hidden unit
// j, NB=2 batch elements per warp, 2048 warps total (3.46/SMSP). Gate pairs
// (i,f)/(g,o) accumulate pre-scaled pre-activations via fma.rn.f32x2; the
// epilogue then needs only ex2+rcp per gate.
// ---------------------------------------------------------------------------
__global__ void __launch_bounds__(WPB * 32, 7) scan_kernel(
    const float* __restrict__ x,
    const float* __restrict__ h0,  const float* __restrict__ c0,
    const float* __restrict__ Wih1,
    const float* __restrict__ bih1, const float* __restrict__ bhh1)
{
    __shared__ ulonglong2 Ws2[(32 - KREG) * 32];   // [(k-KREG)][j] = (wIF, wGO), block-shared
    __shared__ ulonglong2 Hs[WPB][2][32];          // [warp][buf][k] = ((hA,hA),(hB,hB))

    const int j  = threadIdx.x & 31;      // lane = hidden unit
    const int w  = threadIdx.x >> 5;      // warp in block
    const int b0 = (blockIdx.x * WPB + w) * NB;

    // Weight registers for k = 0..KREG-1
    u64 wIFr[KREG], wGOr[KREG];
    #pragma unroll
    for (int k = 0; k < KREG; k++) {
        ulonglong2 ww = g_W1p[k * 32 + j];
        wIFr[k] = ww.x;
        wGOr[k] = ww.y;
    }
    // Remaining k-slices staged once into block-shared smem (both warps help)
    #pragma unroll
    for (int k = KREG + w; k < 32; k += WPB)
        Ws2[(k - KREG) * 32 + j] = g_W1p[k * 32 + j];

    // Per-lane constants: combined bias and input weight, gate-paired, scaled
    const u64 biasIF = pack2(-L2E        * (bih1[0  + j] + bhh1[0  + j]),
                             -L2E        * (bih1[32 + j] + bhh1[32 + j]));
    const u64 biasGO = pack2(-2.0f * L2E * (bih1[64 + j] + bhh1[64 + j]),
                             -L2E        * (bih1[96 + j] + bhh1[96 + j]));
    const u64 wihIF  = pack2(-L2E        * Wih1[0  + j],
                             -L2E        * Wih1[32 + j]);
    const u64 wihGO  = pack2(-2.0f * L2E * Wih1[64 + j],
                             -L2E        * Wih1[96 + j]);

    // Carry c in registers; h lives in the per-warp smem stage
    float c[NB];
    #pragma unroll
    for (int b = 0; b < NB; b++) c[b] = c0[(b0 + b) * HID + j];

    {
        float ha = h0[(b0 + 0) * HID + j];
        float hb = h0[(b0 + 1) * HID + j];
        ulonglong2 hq;
        hq.x = pack2(ha, ha);
        hq.y = pack2(hb, hb);
        Hs[w][0][j] = hq;
    }

    // lanes 0..NB-1 hold x[t][b0+lane]; prefetch one step ahead
    float xc = (j < NB) ? x[b0 + j] : 0.0f;
    __syncthreads();    // weight stage + initial Hs visible

    #pragma unroll 1
    for (int t = 0; t < SEQ; t++) {
        const int rb = t & 1;

        float xn = 0.0f;
        if (j < NB && t + 1 < SEQ) xn = x[(t + 1) * BATCH + b0 + j];

        u64 aIF[NB], aGO[NB];
        #pragma unroll
        for (int b = 0; b < NB; b++) {
            float xb = __shfl_sync(0xffffffffu, xc, b);
            u64 xd = pack2(xb, xb);
            aIF[b] = fma2(xd, wihIF, biasIF);
            aGO[b] = fma2(xd, wihGO, biasGO);
        }

        // recurrent matvec: per k, 1 broadcast LDS.128 (both batches' h) +
        // 4 FFMA2; weights from registers (k<KREG) or shared LDS.128.
        #pragma unroll
        for (int k = 0; k < 32; k++) {
            u64 wIF, wGO;
            if (k < KREG) {
                wIF = wIFr[k];
                wGO = wGOr[k];
            } else {
                ulonglong2 ww = Ws2[(k - KREG) * 32 + j];
                wIF = ww.x;
                wGO = ww.y;
            }
            ulonglong2 hq = Hs[w][rb][k];     // broadcast, pre-paired
            aIF[0] = fma2(hq.x, wIF, aIF[0]);
            aGO[0] = fma2(hq.x, wGO, aGO[0]);
            aIF[1] = fma2(hq.y, wIF, aIF[1]);
            aGO[1] = fma2(hq.y, wGO, aGO[1]);
        }

        float hn[NB];
        #pragma unroll
        for (int b = 0; b < NB; b++) {
            float ai, af, ag, ao;
            unpack2(aIF[b], ai, af);      // pre-scaled by -log2e
            unpack2(aGO[b], ag, ao);      // ag pre-scaled by -2log2e, ao by -log2e
            float ig = sig_s(ai);
            float fg = sig_s(af);
            float gg = tanh_s(ag);
            float og = sig_s(ao);
            c[b]  = fmaf(fg, c[b], ig * gg);
            float tc = tanh_s(c[b] * (-2.0f * L2E));
            hn[b] = og * tc;
        }

        {
            ulonglong2 hq;
            hq.x = pack2(hn[0], hn[0]);
            hq.y = pack2(hn[1], hn[1]);
            Hs[w][rb ^ 1][j] = hq;
        }
        xc = xn;
        __syncwarp();
    }

    // SEQ even -> final h landed in buffer 0. Write [j][b] for the tail.
    {
        ulonglong2 hq = Hs[w][0][j];
        float lo, hi;
        unpack2(hq.x, lo, hi);
        g_hf[j * BATCH + b0 + 0] = lo;
        unpack2(hq.y, lo, hi);
        g_hf[j * BATCH + b0 + 1] = lo;
        g_cf[j * BATCH + b0 + 0] = c[0];
        g_cf[j * BATCH + b0 + 1] = c[1];
    }
}

// ---------------------------------------------------------------------------
// Kernel 2: cell 2 (input = hidden = hf, cell = cf) + FC. One thread per batch.
// Wih2 + Whh2 folded into a single [128,32] matrix.
// ---------------------------------------------------------------------------
__global__ void __launch_bounds__(128) tail_kernel(
    const float* __restrict__ Wih2, const float* __restrict__ Whh2,
    const float* __restrict__ bih2, const float* __restrict__ bhh2,
    const float* __restrict__ Wfc,  const float* __restrict__ bfc,
    float* __restrict__ out)
{
    __shared__ float W2s[128 * 32];
    __shared__ float b2s[128];
    __shared__ float wfcs[32];
    const int tid = threadIdx.x;

    for (int i = tid; i < 128 * 32; i += 128) W2s[i] = Wih2[i] + Whh2[i];
    if (tid < 128) b2s[tid] = bih2[tid] + bhh2[tid];
    if (tid < 32)  wfcs[tid] = Wfc[tid];
    __syncthreads();

    const int b = blockIdx.x * 128 + tid;

    float h[HID];
    #pragma unroll
    for (int k = 0; k < HID; k++) h[k] = g_hf[k * BATCH + b];   // coalesced

    float acc_out = bfc[0];
    #pragma unroll
    for (int jj = 0; jj < HID; jj++) {
        float ai = b2s[0  + jj];
        float af = b2s[32 + jj];
        float ag = b2s[64 + jj];
        float ao = b2s[96 + jj];
        #pragma unroll
        for (int k = 0; k < HID; k++) {
            float hk = h[k];
            ai = fmaf(hk, W2s[(0  + jj) * HID + k], ai);
            af = fmaf(hk, W2s[(32 + jj) * HID + k], af);
            ag = fmaf(hk, W2s[(64 + jj) * HID + k], ag);
            ao = fmaf(hk, W2s[(96 + jj) * HID + k], ao);
        }
        float cf = g_cf[jj * BATCH + b];
        float cn = fmaf(sigf(af), cf, sigf(ai) * tanhf_fast(ag));
        float hn = sigf(ao) * tanhf_fast(cn);
        acc_out = fmaf(hn, wfcs[jj], acc_out);
    }
    out[b] = acc_out;
}

// ---------------------------------------------------------------------------
// kernel_launch: pack -> scan -> tail (default stream, graph-capturable)
// Input order: x,h0,c0,h1,c1,Wih1,Whh1,bih1,bhh1,Wih2,Whh2,bih2,bhh2,Wfc,bfc
// ---------------------------------------------------------------------------
extern "C" void kernel_launch(void* const* d_in, const int* in_sizes, int n_in,
                              void* d_out, int out_size)
{
    const float* x    = (const float*)d_in[0];
    const float* h0   = (const float*)d_in[1];
    const float* c0   = (const float*)d_in[2];
    const float* Wih1 = (const float*)d_in[5];
    const float* Whh1 = (const float*)d_in[6];
    const float* bih1 = (const float*)d_in[7];
    const float* bhh1 = (const float*)d_in[8];
    const float* Wih2 = (const float*)d_in[9];
    const float* Whh2 = (const float*)d_in[10];
    const float* bih2 = (const float*)d_in[11];
    const float* bhh2 = (const float*)d_in[12];
    const float* Wfc  = (const float*)d_in[13];
    const float* bfc  = (const float*)d_in[14];
    float* out = (float*)d_out;

    pack_kernel<<<8, 128>>>(Whh1);
    scan_kernel<<<BATCH / (NB * WPB), WPB * 32>>>(x, h0, c0, Wih1, bih1, bhh1);
    tail_kernel<<<BATCH / 128, 128>>>(Wih2, Whh2, bih2, bhh2, Wfc, bfc, out);
}

// round 6
// speedup vs baseline: 1.1026x; 1.0330x over previous
#include <cuda_runtime.h>
#include <cuda_bf16.h>

// Problem constants
#define BATCH 4096
#define SEQ   512
#define HID   32
#define NB    4            // batch elements per warp; 1024 one-warp blocks

#define L2E   1.4426950408889634f    // log2(e)

using u64 = unsigned long long;

// ---- packed f32x2 helpers (FFMA2 path, PTX-only) ----
__device__ __forceinline__ u64 pack2(float lo, float hi) {
    u64 r; asm("mov.b64 %0, {%1, %2};" : "=l"(r) : "f"(lo), "f"(hi)); return r;
}
__device__ __forceinline__ void unpack2(u64 v, float& lo, float& hi) {
    asm("mov.b64 {%0, %1}, %2;" : "=f"(lo), "=f"(hi) : "l"(v));
}
__device__ __forceinline__ u64 fma2(u64 a, u64 b, u64 c) {
    u64 d; asm("fma.rn.f32x2 %0, %1, %2, %3;" : "=l"(d) : "l"(a), "l"(b), "l"(c)); return d;
}
__device__ __forceinline__ float lo2(u64 v) {
    float lo, hi; unpack2(v, lo, hi); return lo;
}

// ---- raw MUFU helpers ----
__device__ __forceinline__ float ex2f(float v) {
    float r; asm("ex2.approx.f32 %0, %1;" : "=f"(r) : "f"(v)); return r;
}
__device__ __forceinline__ float rcpf(float v) {
    float r; asm("rcp.approx.f32 %0, %1;" : "=f"(r) : "f"(v)); return r;
}
// a_scaled = -log2(e) * a   -> sigmoid(a)
__device__ __forceinline__ float sig_s(float a_scaled) {
    return rcpf(1.0f + ex2f(a_scaled));
}
// a_scaled = -2*log2(e) * a -> tanh(a)
__device__ __forceinline__ float tanh_s(float a_scaled) {
    return fmaf(2.0f, rcpf(1.0f + ex2f(a_scaled)), -1.0f);
}
// exact-path (same units) activations for the tail section
__device__ __forceinline__ float sigf(float v) {
    return __fdividef(1.0f, 1.0f + __expf(-v));
}
__device__ __forceinline__ float tanhf_fast(float v) {
    return __fdividef(2.0f, 1.0f + __expf(-2.0f * v)) - 1.0f;
}

// ---------------------------------------------------------------------------
// Single fused kernel: inline weight pack -> 512-step scan -> cell2 + FC.
// 1024 one-warp blocks; lane = hidden unit j; NB=4 batches per warp.
// All Whh1 weights live in registers (64 u64 pairs / lane). h travels through
// a tiny per-warp double-buffered smem stage as duplicated f32 pairs so every
// FFMA2 operand is load-ready (zero repacks in the hot loop).
// ---------------------------------------------------------------------------
__global__ void __launch_bounds__(32) lstm_kernel(
    const float* __restrict__ x,
    const float* __restrict__ h0,   const float* __restrict__ c0,
    const float* __restrict__ Wih1, const float* __restrict__ Whh1,
    const float* __restrict__ bih1, const float* __restrict__ bhh1,
    const float* __restrict__ Wih2, const float* __restrict__ Whh2,
    const float* __restrict__ bih2, const float* __restrict__ bhh2,
    const float* __restrict__ Wfc,  const float* __restrict__ bfc,
    float* __restrict__ out)
{
    __shared__ ulonglong2 Hs[2][NB / 2][32];   // [buf][pair][k] = ((hA,hA),(hB,hB))

    const int j  = threadIdx.x;          // lane = hidden unit
    const int b0 = blockIdx.x * NB;

    // ---- inline pack: all 32 k-slices of scaled Whh1 into registers ----
    u64 wIFr[32], wGOr[32];
    {
        const float4* W1v = reinterpret_cast<const float4*>(Whh1);
        #pragma unroll
        for (int q = 0; q < 8; q++) {
            float4 wi = W1v[(0  + j) * 8 + q];
            float4 wf = W1v[(32 + j) * 8 + q];
            float4 wg = W1v[(64 + j) * 8 + q];
            float4 wo = W1v[(96 + j) * 8 + q];
            wIFr[4 * q + 0] = pack2(-L2E * wi.x, -L2E * wf.x);
            wIFr[4 * q + 1] = pack2(-L2E * wi.y, -L2E * wf.y);
            wIFr[4 * q + 2] = pack2(-L2E * wi.z, -L2E * wf.z);
            wIFr[4 * q + 3] = pack2(-L2E * wi.w, -L2E * wf.w);
            wGOr[4 * q + 0] = pack2(-2.0f * L2E * wg.x, -L2E * wo.x);
            wGOr[4 * q + 1] = pack2(-2.0f * L2E * wg.y, -L2E * wo.y);
            wGOr[4 * q + 2] = pack2(-2.0f * L2E * wg.z, -L2E * wo.z);
            wGOr[4 * q + 3] = pack2(-2.0f * L2E * wg.w, -L2E * wo.w);
        }
    }

    // Per-lane constants: combined bias and input weight, gate-paired, scaled
    const u64 biasIF = pack2(-L2E        * (bih1[0  + j] + bhh1[0  + j]),
                             -L2E        * (bih1[32 + j] + bhh1[32 + j]));
    const u64 biasGO = pack2(-2.0f * L2E * (bih1[64 + j] + bhh1[64 + j]),
                             -L2E        * (bih1[96 + j] + bhh1[96 + j]));
    const u64 wihIF  = pack2(-L2E        * Wih1[0  + j],
                             -L2E        * Wih1[32 + j]);
    const u64 wihGO  = pack2(-2.0f * L2E * Wih1[64 + j],
                             -L2E        * Wih1[96 + j]);

    // Carry c in registers; h lives in the smem stage
    float c[NB];
    #pragma unroll
    for (int b = 0; b < NB; b++) c[b] = c0[(b0 + b) * HID + j];

    #pragma unroll
    for (int g = 0; g < NB / 2; g++) {
        float ha = h0[(b0 + 2 * g)     * HID + j];
        float hb = h0[(b0 + 2 * g + 1) * HID + j];
        ulonglong2 hq;
        hq.x = pack2(ha, ha);
        hq.y = pack2(hb, hb);
        Hs[0][g][j] = hq;
    }

    // lanes 0..NB-1 hold x[t][b0+lane]; prefetch one step ahead
    float xc = (j < NB) ? x[b0 + j] : 0.0f;
    __syncwarp();

    // ---------------- 512-step recurrence ----------------
    #pragma unroll 1
    for (int t = 0; t < SEQ; t++) {
        const int rb = t & 1;

        float xn = 0.0f;
        if (j < NB && t + 1 < SEQ) xn = x[(t + 1) * BATCH + b0 + j];

        u64 aIF[NB], aGO[NB];
        #pragma unroll
        for (int b = 0; b < NB; b++) {
            float xb = __shfl_sync(0xffffffffu, xc, b);
            u64 xd = pack2(xb, xb);
            aIF[b] = fma2(xd, wihIF, biasIF);
            aGO[b] = fma2(xd, wihGO, biasGO);
        }

        // recurrent matvec: per k, 2 broadcast LDS.128 + 8 FFMA2, weights all
        // from registers.
        #pragma unroll
        for (int k = 0; k < 32; k++) {
            u64 wIF = wIFr[k];
            u64 wGO = wGOr[k];
            #pragma unroll
            for (int g = 0; g < NB / 2; g++) {
                ulonglong2 hq = Hs[rb][g][k];     // broadcast, pre-paired
                aIF[2 * g]     = fma2(hq.x, wIF, aIF[2 * g]);
                aGO[2 * g]     = fma2(hq.x, wGO, aGO[2 * g]);
                aIF[2 * g + 1] = fma2(hq.y, wIF, aIF[2 * g + 1]);
                aGO[2 * g + 1] = fma2(hq.y, wGO, aGO[2 * g + 1]);
            }
        }

        float hn[NB];
        #pragma unroll
        for (int b = 0; b < NB; b++) {
            float ai, af, ag, ao;
            unpack2(aIF[b], ai, af);      // pre-scaled by -log2e
            unpack2(aGO[b], ag, ao);      // ag by -2log2e, ao by -log2e
            float ig = sig_s(ai);
            float fg = sig_s(af);
            float gg = tanh_s(ag);
            float og = sig_s(ao);
            c[b]  = fmaf(fg, c[b], ig * gg);
            hn[b] = og * tanh_s(c[b] * (-2.0f * L2E));
        }

        #pragma unroll
        for (int g = 0; g < NB / 2; g++) {
            ulonglong2 hq;
            hq.x = pack2(hn[2 * g],     hn[2 * g]);
            hq.y = pack2(hn[2 * g + 1], hn[2 * g + 1]);
            Hs[rb ^ 1][g][j] = hq;
        }
        xc = xn;
        __syncwarp();
    }

    // ---------------- inline tail: cell 2 + FC (exact path) ----------------
    // SEQ even -> final h is in Hs[0]; c[] holds final cell state.
    float a2i[NB], a2f[NB], a2g[NB], a2o[NB];
    {
        float bi2 = bih2[0  + j] + bhh2[0  + j];
        float bf2 = bih2[32 + j] + bhh2[32 + j];
        float bg2 = bih2[64 + j] + bhh2[64 + j];
        float bo2 = bih2[96 + j] + bhh2[96 + j];
        #pragma unroll
        for (int b = 0; b < NB; b++) {
            a2i[b] = bi2; a2f[b] = bf2; a2g[b] = bg2; a2o[b] = bo2;
        }
    }
    {
        const float4* Wi2v = reinterpret_cast<const float4*>(Wih2);
        const float4* Wh2v = reinterpret_cast<const float4*>(Whh2);
        #pragma unroll
        for (int q = 0; q < 8; q++) {
            // combined W2 = Wih2 + Whh2, gate rows for this lane's j
            float4 wi = Wi2v[(0  + j) * 8 + q], hi_ = Wh2v[(0  + j) * 8 + q];
            float4 wf = Wi2v[(32 + j) * 8 + q], hf_ = Wh2v[(32 + j) * 8 + q];
            float4 wg = Wi2v[(64 + j) * 8 + q], hg_ = Wh2v[(64 + j) * 8 + q];
            float4 wo = Wi2v[(96 + j) * 8 + q], ho_ = Wh2v[(96 + j) * 8 + q];
            float ci2[4] = { wi.x + hi_.x, wi.y + hi_.y, wi.z + hi_.z, wi.w + hi_.w };
            float cf2[4] = { wf.x + hf_.x, wf.y + hf_.y, wf.z + hf_.z, wf.w + hf_.w };
            float cg2[4] = { wg.x + hg_.x, wg.y + hg_.y, wg.z + hg_.z, wg.w + hg_.w };
            float co2[4] = { wo.x + ho_.x, wo.y + ho_.y, wo.z + ho_.z, wo.w + ho_.w };
            #pragma unroll
            for (int kk = 0; kk < 4; kk++) {
                int k = 4 * q + kk;
                ulonglong2 hq0 = Hs[0][0][k];
                ulonglong2 hq1 = Hs[0][1][k];
                float hk[NB] = { lo2(hq0.x), lo2(hq0.y), lo2(hq1.x), lo2(hq1.y) };
                #pragma unroll
                for (int b = 0; b < NB; b++) {
                    a2i[b] = fmaf(hk[b], ci2[kk], a2i[b]);
                    a2f[b] = fmaf(hk[b], cf2[kk], a2f[b]);
                    a2g[b] = fmaf(hk[b], cg2[kk], a2g[b]);
                    a2o[b] = fmaf(hk[b], co2[kk], a2o[b]);
                }
            }
        }
    }

    const float wfc_j = Wfc[j];
    const float bfc0  = bfc[0];
    #pragma unroll
    for (int b = 0; b < NB; b++) {
        float cn  = fmaf(sigf(a2f[b]), c[b], sigf(a2i[b]) * tanhf_fast(a2g[b]));
        float h1f = sigf(a2o[b]) * tanhf_fast(cn);
        float v = h1f * wfc_j;
        #pragma unroll
        for (int m = 16; m > 0; m >>= 1)
            v += __shfl_xor_sync(0xffffffffu, v, m);
        if (j == 0) out[b0 + b] = v + bfc0;
    }
}

// ---------------------------------------------------------------------------
// kernel_launch: single fused launch (graph-capturable)
// Input order: x,h0,c0,h1,c1,Wih1,Whh1,bih1,bhh1,Wih2,Whh2,bih2,bhh2,Wfc,bfc
// ---------------------------------------------------------------------------
extern "C" void kernel_launch(void* const* d_in, const int* in_sizes, int n_in,
                              void* d_out, int out_size)
{
    const float* x    = (const float*)d_in[0];
    const float* h0   = (const float*)d_in[1];
    const float* c0   = (const float*)d_in[2];
    const float* Wih1 = (const float*)d_in[5];
    const float* Whh1 = (const float*)d_in[6];
    const float* bih1 = (const float*)d_in[7];
    const float* bhh1 = (const float*)d_in[8];
    const float* Wih2 = (const float*)d_in[9];
    const float* Whh2 = (const float*)d_in[10];
    const float* bih2 = (const float*)d_in[11];
    const float* bhh2 = (const float*)d_in[12];
    const float* Wfc  = (const float*)d_in[13];
    const float* bfc  = (const float*)d_in[14];
    float* out = (float*)d_out;

    lstm_kernel<<<BATCH / NB, 32>>>(x, h0, c0, Wih1, Whh1, bih1, bhh1,
                                    Wih2, Whh2, bih2, bhh2, Wfc, bfc, out);
}